// round 17
// baseline (speedup 1.0000x reference)
#include <cuda_runtime.h>
#include <cuda_fp16.h>
#include <mma.h>
#include <cstdint>

using namespace nvcuda;

// ---------------- problem constants ----------------
#define BATCH   256
#define INSTRS  64
#define TOKENS  16
#define HID     256
#define EMB     256
#define FOURH   1024
#define KTOT    512
#define NTOK    (BATCH*INSTRS)   // 16384

// ---------------- token GEMM (R16 champion): BM=64, BN=64, BK=64, 2-stage ----------------
#define TBM 64
#define BN  64
#define BK  64
#define LDSH 72                  // BK + 8 pad
#define NK  (KTOT/BK)            // 8
#define CLD 68                   // token epilogue Cs stride (floats)
// smem: As[2][64*72]h = 18432 @0 (Cs [64][68]f = 17408 overlays),
//       Bs[2][64*72]h = 18432 @18432, Aidx @36864, Arow @37120
#define T_BS_OFF   18432
#define T_AIDX_OFF 36864
#define T_AROW_OFF 37120
#define SMEM_TOK   37632

// ---------------- instr GEMM: IBM=64, IBN=16, 128 threads (256 blocks ~ 2 CTA/SM) ----------------
#define IBM 64
#define IBN 16
#define ICLD 20                  // instr epilogue Cs stride (floats)
// smem: As[2][64*72]h = 18432 @0 (Cs [64][20]f = 5120 overlays),
//       Bs[2][16*72]h = 4608 @18432, Aidx @23040
#define I_BS_OFF   18432
#define I_AIDX_OFF 23040
#define SMEM_INS   23296

// ---------------- device state ----------------
// h ping-ponged by step parity: step t reads h[(t&1)^1], writes h[t&1].
__device__ __half g_h_tok[2][(size_t)NTOK * HID];
__device__ float  g_c_tok[(size_t)NTOK * HID];
__device__ __half g_h_ins[2][(size_t)BATCH * HID];
__device__ float  g_c_ins[(size_t)BATCH * HID];
__device__ __half g_instr_repr[(size_t)NTOK * HID];
__device__ int    g_perm_tok[NTOK];
__device__ int    g_cnt_tok[TOKENS];
__device__ int    g_perm_ins[BATCH];
__device__ int    g_cnt_ins[INSTRS];
// pre-converted fp16 operands
__device__ __half g_emb_h[(size_t)4096 * EMB];
__device__ __half g_W_tok[(size_t)FOURH * KTOT];   // [jp][512], gate-interleaved
__device__ __half g_W_ins[(size_t)FOURH * KTOT];

#define CP_ASYNC16(dst, src) \
    asm volatile("cp.async.cg.shared.global [%0], [%1], 16;" :: "r"(dst), "l"(src))
#define CP_COMMIT  asm volatile("cp.async.commit_group;")
#define CP_WAIT0   asm volatile("cp.async.wait_group 0;")

// ================= token phase: R16 champion body + fused gather =================
template<bool FIRST>
__global__ void __launch_bounds__(256)
tok_step(int t, const int* __restrict__ tok,
         const float* __restrict__ bias, const int* __restrict__ ntok)
{
    if (blockIdx.x * TBM >= g_cnt_tok[t]) return;

    constexpr int NKE = FIRST ? 4 : NK;

    extern __shared__ char smraw[];
    __half*        As   = (__half*)smraw;                    // [2][64*LDSH]
    __half*        Bs   = (__half*)(smraw + T_BS_OFF);       // [2][64*LDSH]
    int*           Aidx = (int*)(smraw + T_AIDX_OFF);
    const __half** Arow = (const __half**)(smraw + T_AROW_OFF);
    float*         Cs   = (float*)smraw;                     // overlay [64][CLD]

    const int m0  = blockIdx.x * TBM;
    const int n0  = blockIdx.y * BN;
    const int tid = threadIdx.x;
    const int wp  = t & 1;
    const int rp  = wp ^ 1;
    const __half* hbase = g_h_tok[rp];

    if (tid < TBM) {
        int n = g_perm_tok[m0 + tid];
        Aidx[tid] = n;
        Arow[tid] = g_emb_h + (size_t)__ldg(&tok[n * TOKENS + t]) * EMB;
    }
    __syncthreads();

    auto issue = [&](int kt, int buf) {
        __half* Ad = As + buf * TBM * LDSH;
#pragma unroll
        for (int i = 0; i < 2; ++i) {
            int c  = tid + i * 256;
            int r  = c >> 3;
            int c8 = (c & 7) << 3;
            const __half* src = (FIRST || kt < 4)
                ? Arow[r] + kt * BK + c8
                : hbase + (size_t)Aidx[r] * HID + (kt - 4) * BK + c8;
            uint32_t dst = (uint32_t)__cvta_generic_to_shared(Ad + r * LDSH + c8);
            CP_ASYNC16(dst, src);
        }
        __half* Bd = Bs + buf * BN * LDSH;
#pragma unroll
        for (int i = 0; i < 2; ++i) {
            int c  = tid + i * 256;
            int r  = c >> 3;
            int c8 = (c & 7) << 3;
            const __half* src = g_W_tok + (size_t)(n0 + r) * KTOT + kt * BK + c8;
            uint32_t dst = (uint32_t)__cvta_generic_to_shared(Bd + r * LDSH + c8);
            CP_ASYNC16(dst, src);
        }
        CP_COMMIT;
    };

    wmma::fragment<wmma::accumulator, 16, 16, 16, float> cf[2];
#pragma unroll
    for (int ni = 0; ni < 2; ++ni)
        wmma::fill_fragment(cf[ni], 0.0f);

    const int warp = tid >> 5;
    const int wm   = warp >> 1;   // 0..3: 16-row slice
    const int wn   = warp & 1;    // 0..1: 32-col slice

    issue(0, 0);
    for (int kt = 0; kt < NKE; ++kt) {
        CP_WAIT0;
        __syncthreads();
        if (kt + 1 < NKE) issue(kt + 1, (kt + 1) & 1);
        const __half* Ab = As + (kt & 1) * TBM * LDSH;
        const __half* Bb = Bs + (kt & 1) * BN * LDSH;
#pragma unroll
        for (int kk = 0; kk < BK; kk += 16) {
            wmma::fragment<wmma::matrix_a, 16, 16, 16, __half, wmma::row_major> a;
            wmma::fragment<wmma::matrix_b, 16, 16, 16, __half, wmma::col_major> b[2];
            wmma::load_matrix_sync(a, Ab + (wm * 16) * LDSH + kk, LDSH);
#pragma unroll
            for (int ni = 0; ni < 2; ++ni)
                wmma::load_matrix_sync(b[ni], Bb + (wn * 32 + ni * 16) * LDSH + kk, LDSH);
#pragma unroll
            for (int ni = 0; ni < 2; ++ni)
                wmma::mma_sync(cf[ni], a, b[ni], cf[ni]);
        }
    }

    __syncthreads();
#pragma unroll
    for (int ni = 0; ni < 2; ++ni)
        wmma::store_matrix_sync(&Cs[(wm * 16) * CLD + wn * 32 + ni * 16],
                                cf[ni], CLD, wmma::mem_row_major);
    __syncthreads();

    {
        int r = tid >> 2;                  // 64 rows, 4 threads/row
        int n = Aidx[r];
        int L = __ldg(&ntok[n]);
        if (t < L) {
            __half* hp = g_h_tok[wp];
            float*  cp = g_c_tok;
            const bool last = (t == L - 1);
            int dg0 = (n0 >> 2) + (tid & 3) * 4;
#pragma unroll
            for (int i = 0; i < 4; ++i) {
                int dl = (tid & 3) * 4 + i;
                int dg = dg0 + i;
                float gi = Cs[r * CLD + dl * 4 + 0] + __ldg(&bias[dg]);
                float gf = Cs[r * CLD + dl * 4 + 1] + __ldg(&bias[256 + dg]);
                float gg = Cs[r * CLD + dl * 4 + 2] + __ldg(&bias[512 + dg]);
                float go = Cs[r * CLD + dl * 4 + 3] + __ldg(&bias[768 + dg]);
                float i_ = 1.0f / (1.0f + expf(-gi));
                float f_ = 1.0f / (1.0f + expf(-gf));
                float g_ = tanhf(gg);
                float o_ = 1.0f / (1.0f + expf(-go));
                size_t idx = (size_t)n * HID + dg;
                float cn = f_ * cp[idx] + i_ * g_;
                cp[idx] = cn;
                __half hv = __float2half_rn(o_ * tanhf(cn));
                hp[idx] = hv;
                if (last) g_instr_repr[idx] = hv;    // fused gather
            }
        }
    }
}

// ================= instr phase: IBM=64, IBN=16, 128 threads, 256 blocks (~2 CTA/SM) =================
template<bool FIRST>
__global__ void __launch_bounds__(128)
ins_step(int s, const float* __restrict__ bias, const int* __restrict__ ninstr)
{
    if (blockIdx.x * IBM >= g_cnt_ins[s]) return;

    constexpr int NKE = FIRST ? 4 : NK;

    extern __shared__ char smraw[];
    __half* As   = (__half*)smraw;                      // [2][IBM*LDSH]
    __half* Bs   = (__half*)(smraw + I_BS_OFF);         // [2][IBN*LDSH]
    int*    Aidx = (int*)(smraw + I_AIDX_OFF);
    float*  Cs   = (float*)smraw;                       // overlay [64][ICLD]

    const int m0  = blockIdx.x * IBM;
    const int n0  = blockIdx.y * IBN;
    const int tid = threadIdx.x;
    const int wp  = s & 1;
    const int rp  = wp ^ 1;
    const __half* hbase = g_h_ins[rp];

    if (tid < IBM) Aidx[tid] = g_perm_ins[m0 + tid];
    __syncthreads();

    auto issue = [&](int kt, int buf) {
        __half* Ad = As + buf * IBM * LDSH;
        // A tile: 64x64 half = 512 chunks, 4/thread (128 threads)
#pragma unroll
        for (int i = 0; i < 4; ++i) {
            int c  = tid + i * 128;
            int r  = c >> 3;
            int c8 = (c & 7) << 3;
            int n  = Aidx[r];
            const __half* src = (FIRST || kt < 4)
                ? g_instr_repr + ((size_t)n * INSTRS + s) * HID + kt * BK + c8
                : hbase + (size_t)n * HID + (kt - 4) * BK + c8;
            uint32_t dst = (uint32_t)__cvta_generic_to_shared(Ad + r * LDSH + c8);
            CP_ASYNC16(dst, src);
        }
        __half* Bd = Bs + buf * IBN * LDSH;
        {
            // B tile: 16x64 half = 128 chunks, 1/thread
            int r  = tid >> 3;
            int c8 = (tid & 7) << 3;
            const __half* src = g_W_ins + (size_t)(n0 + r) * KTOT + kt * BK + c8;
            uint32_t dst = (uint32_t)__cvta_generic_to_shared(Bd + r * LDSH + c8);
            CP_ASYNC16(dst, src);
        }
        CP_COMMIT;
    };

    wmma::fragment<wmma::accumulator, 16, 16, 16, float> cf;
    wmma::fill_fragment(cf, 0.0f);

    const int warp = tid >> 5;          // 0..3: 16-row slice; single 16-col n tile

    issue(0, 0);
    for (int kt = 0; kt < NKE; ++kt) {
        CP_WAIT0;
        __syncthreads();
        if (kt + 1 < NKE) issue(kt + 1, (kt + 1) & 1);
        const __half* Ab = As + (kt & 1) * IBM * LDSH;
        const __half* Bb = Bs + (kt & 1) * IBN * LDSH;
#pragma unroll
        for (int kk = 0; kk < BK; kk += 16) {
            wmma::fragment<wmma::matrix_a, 16, 16, 16, __half, wmma::row_major> a;
            wmma::fragment<wmma::matrix_b, 16, 16, 16, __half, wmma::col_major> b;
            wmma::load_matrix_sync(a, Ab + (warp * 16) * LDSH + kk, LDSH);
            wmma::load_matrix_sync(b, Bb + kk, LDSH);
            wmma::mma_sync(cf, a, b, cf);
        }
    }

    __syncthreads();
    wmma::store_matrix_sync(&Cs[(warp * 16) * ICLD], cf, ICLD, wmma::mem_row_major);
    __syncthreads();

    {
        int r = tid >> 1;                 // 64 rows, 2 threads/row, 2 d's each
        int n = Aidx[r];
        int L = __ldg(&ninstr[n]);
        if (s < L) {
            __half* hp = g_h_ins[wp];
            float*  cp = g_c_ins;
            int dbase = n0 >> 2;          // 4 d's per block
#pragma unroll
            for (int i = 0; i < 2; ++i) {
                int dl = (tid & 1) * 2 + i;   // 0..3
                int dg = dbase + dl;
                float gi = Cs[r * ICLD + dl * 4 + 0] + __ldg(&bias[dg]);
                float gf = Cs[r * ICLD + dl * 4 + 1] + __ldg(&bias[256 + dg]);
                float gg = Cs[r * ICLD + dl * 4 + 2] + __ldg(&bias[512 + dg]);
                float go = Cs[r * ICLD + dl * 4 + 3] + __ldg(&bias[768 + dg]);
                float i_ = 1.0f / (1.0f + expf(-gi));
                float f_ = 1.0f / (1.0f + expf(-gf));
                float g_ = tanhf(gg);
                float o_ = 1.0f / (1.0f + expf(-go));
                size_t idx = (size_t)n * HID + dg;
                float cn = f_ * cp[idx] + i_ * g_;
                cp[idx] = cn;
                hp[idx] = __float2half_rn(o_ * tanhf(cn));
            }
        }
    }
}

// merged prep: weights (gate-interleaved [jp][512]) + embedding -> fp16
__global__ void __launch_bounds__(256)
prep_all(const float* __restrict__ WihT, const float* __restrict__ WhhT,
         const float* __restrict__ WihI, const float* __restrict__ WhhI,
         const float* __restrict__ emb)
{
    int idx = blockIdx.x * 256 + threadIdx.x;      // grid covers 4096*256
    g_emb_h[idx] = __float2half_rn(emb[idx]);
    if (idx < FOURH * KTOT) {
        int jp = idx >> 9;
        int k  = idx & 511;
        int j  = (jp & 3) * 256 + (jp >> 2);
        float v = (k < 256) ? WihT[j * 256 + k] : WhhT[j * 256 + (k - 256)];
        g_W_tok[idx] = __float2half_rn(v);
        float u = (k < 256) ? WihI[j * 256 + k] : WhhI[j * 256 + (k - 256)];
        g_W_ins[idx] = __float2half_rn(u);
    }
}

// counting sort by length (descending) + active-count table
__global__ void build_perm(const int* __restrict__ ntok,
                           const int* __restrict__ ninstr)
{
    __shared__ int hist[65];
    __shared__ int off[65];
    if (blockIdx.x == 0) {
        for (int i = threadIdx.x; i < 17; i += blockDim.x) hist[i] = 0;
        __syncthreads();
        for (int i = threadIdx.x; i < NTOK; i += blockDim.x)
            atomicAdd(&hist[ntok[i]], 1);
        __syncthreads();
        if (threadIdx.x == 0) {
            int acc = 0;
            for (int l = 16; l >= 0; --l) { off[l] = acc; acc += hist[l]; }
            for (int t = 0; t < TOKENS; ++t) g_cnt_tok[t] = off[t];
        }
        __syncthreads();
        for (int i = threadIdx.x; i < NTOK; i += blockDim.x) {
            int p = atomicAdd(&off[ntok[i]], 1);
            g_perm_tok[p] = i;
        }
    } else {
        for (int i = threadIdx.x; i < 65; i += blockDim.x) hist[i] = 0;
        __syncthreads();
        for (int i = threadIdx.x; i < BATCH; i += blockDim.x)
            atomicAdd(&hist[ninstr[i]], 1);
        __syncthreads();
        if (threadIdx.x == 0) {
            int acc = 0;
            for (int l = 64; l >= 0; --l) { off[l] = acc; acc += hist[l]; }
            for (int s = 0; s < INSTRS; ++s) g_cnt_ins[s] = off[s];
        }
        __syncthreads();
        for (int i = threadIdx.x; i < BATCH; i += blockDim.x) {
            int p = atomicAdd(&off[ninstr[i]], 1);
            g_perm_ins[p] = i;
        }
    }
}

__global__ void __launch_bounds__(256) zero_state()
{
    int idx = blockIdx.x * 256 + threadIdx.x;   // grid covers NTOK*HID
    g_h_tok[0][idx] = __half(0.0f);
    g_h_tok[1][idx] = __half(0.0f);
    g_c_tok[idx]    = 0.0f;
    g_instr_repr[idx] = __half(0.0f);           // rows with len==0 keep zeros
    if (idx < BATCH * HID) {
        g_h_ins[0][idx] = __half(0.0f);
        g_h_ins[1][idx] = __half(0.0f);
        g_c_ins[idx]    = 0.0f;
    }
}

__global__ void __launch_bounds__(256)
final_linear(const int* __restrict__ ninstr,
             const float* __restrict__ linW,
             const float* __restrict__ linb,
             float* __restrict__ out)
{
    int b = blockIdx.x, tid = threadIdx.x;
    int L = ninstr[b];
    float h = (L > 0) ? __half2float(g_h_ins[(L - 1) & 1][(size_t)b * HID + tid]) : 0.0f;
    float v = h * linW[tid];
#pragma unroll
    for (int o = 16; o > 0; o >>= 1) v += __shfl_down_sync(0xffffffffu, v, o);
    __shared__ float red[8];
    if ((tid & 31) == 0) red[tid >> 5] = v;
    __syncthreads();
    if (tid < 8) {
        float s = red[tid];
#pragma unroll
        for (int o = 4; o > 0; o >>= 1) s += __shfl_down_sync(0xffu, s, o);
        if (tid == 0) out[b] = s + linb[0];
    }
}

extern "C" void kernel_launch(void* const* d_in, const int* in_sizes, int n_in,
                              void* d_out, int out_size)
{
    const int*   blocks = (const int*)d_in[0];
    const int*   ninstr = (const int*)d_in[1];
    const int*   ntok   = (const int*)d_in[2];
    const float* emb    = (const float*)d_in[3];
    const float* WihT   = (const float*)d_in[4];
    const float* WhhT   = (const float*)d_in[5];
    const float* bT     = (const float*)d_in[6];
    const float* WihI   = (const float*)d_in[7];
    const float* WhhI   = (const float*)d_in[8];
    const float* bI     = (const float*)d_in[9];
    const float* linW   = (const float*)d_in[10];
    const float* linb   = (const float*)d_in[11];
    float* out = (float*)d_out;
    (void)in_sizes; (void)n_in; (void)out_size;

    cudaFuncSetAttribute(tok_step<true>,  cudaFuncAttributeMaxDynamicSharedMemorySize, SMEM_TOK);
    cudaFuncSetAttribute(tok_step<false>, cudaFuncAttributeMaxDynamicSharedMemorySize, SMEM_TOK);
    cudaFuncSetAttribute(ins_step<true>,  cudaFuncAttributeMaxDynamicSharedMemorySize, SMEM_INS);
    cudaFuncSetAttribute(ins_step<false>, cudaFuncAttributeMaxDynamicSharedMemorySize, SMEM_INS);

    zero_state<<<NTOK * HID / 256, 256>>>();
    build_perm<<<2, 512>>>(ntok, ninstr);
    prep_all<<<4096 * EMB / 256, 256>>>(WihT, WhhT, WihI, WhhI, emb);

    {
        dim3 grid(NTOK / TBM, FOURH / BN);             // 256 x 16, blocks self-trim
        tok_step<true><<<grid, 256, SMEM_TOK>>>(0, blocks, bT, ntok);
        for (int t = 1; t < TOKENS; ++t)
            tok_step<false><<<grid, 256, SMEM_TOK>>>(t, blocks, bT, ntok);
    }
    {
        dim3 grid(BATCH / IBM, FOURH / IBN);           // 4 x 64 = 256 blocks
        ins_step<true><<<grid, 128, SMEM_INS>>>(0, bI, ninstr);
        for (int s = 1; s < INSTRS; ++s)
            ins_step<false><<<grid, 128, SMEM_INS>>>(s, bI, ninstr);
    }
    final_linear<<<BATCH, 256>>>(ninstr, linW, linb, out);
}